// round 6
// baseline (speedup 1.0000x reference)
#include <cuda_runtime.h>
#include <cuda_bf16.h>
#include <cstdint>

#define ALPHA 0.2f
#define KDIM 4096
#define NDIM 1024
#define CH 16
#define NCHUNK (KDIM / CH)   // 256

// ---------------- scratch (__device__ globals; no allocs allowed) ----------
__device__ float g_s1[KDIM], g_s2[KDIM];
__device__ float g_ea[KDIM], g_ec[KDIM];        // exp(s1), exp(0.2 s1)
__device__ float g_eb[KDIM], g_ed[KDIM];        // exp(s2), exp(0.2 s2)
__device__ float g_sorted[KDIM];                // s2 ascending
__device__ int   g_sigma[KDIM];                 // sorted rank -> original index
__device__ float g_ebS[KDIM], g_edS[KDIM];      // eb/ed in sorted order
__device__ float g_sb[KDIM + 1], g_sd[KDIM + 1];// scalar global suffix sums
__device__ float g_totBc[NCHUNK * NDIM];        // per-chunk totals (1MB each)
__device__ float g_totDc[NCHUNK * NDIM];
__device__ float g_carB[NCHUNK * NDIM];         // exclusive suffix carries
__device__ float g_carD[NCHUNK * NDIM];
__device__ float g_totD[NDIM];                  // full TotD vector
// row -> emission metadata
__device__ float g_aZ[KDIM], g_cZ[KDIM];
__device__ int   g_tloc[KDIM];                  // local rank in chunk, or -1 (neg-only)
__device__ int   g_bkt[KDIM], g_slot[KDIM];
__device__ int   g_bcnt[NCHUNK];
__device__ int   g_boff[NCHUNK + 1];
__device__ int   g_list[KDIM];                  // rows grouped by bucket

// ---------------------------------------------------------------------------
// K1: s1[i] = x[i,:].w1 ; s2[i] = x[i,:].w2 ; plus the 4 exp factors
// ---------------------------------------------------------------------------
__global__ void k_scores(const float* __restrict__ x, const float* __restrict__ w) {
    int i = blockIdx.x;
    int t = threadIdx.x;  // 256 threads * float4 = 1024
    const float4* xr = reinterpret_cast<const float4*>(x + (size_t)i * NDIM);
    const float4* w1 = reinterpret_cast<const float4*>(w);
    const float4* w2 = reinterpret_cast<const float4*>(w + NDIM);
    float4 xv = xr[t];
    float4 a = w1[t];
    float4 b = w2[t];
    float d1 = xv.x * a.x + xv.y * a.y + xv.z * a.z + xv.w * a.w;
    float d2 = xv.x * b.x + xv.y * b.y + xv.z * b.z + xv.w * b.w;
    #pragma unroll
    for (int o = 16; o > 0; o >>= 1) {
        d1 += __shfl_down_sync(0xffffffffu, d1, o);
        d2 += __shfl_down_sync(0xffffffffu, d2, o);
    }
    __shared__ float sm1[8], sm2[8];
    if ((t & 31) == 0) { sm1[t >> 5] = d1; sm2[t >> 5] = d2; }
    __syncthreads();
    if (t == 0) {
        float s1 = 0.f, s2 = 0.f;
        #pragma unroll
        for (int q = 0; q < 8; q++) { s1 += sm1[q]; s2 += sm2[q]; }
        g_s1[i] = s1;
        g_s2[i] = s2;
        g_ea[i] = __expf(s1);
        g_ec[i] = __expf(ALPHA * s1);
        g_eb[i] = __expf(s2);
        g_ed[i] = __expf(ALPHA * s2);
    }
}

// ---------------------------------------------------------------------------
// K2: ranks, 16 rows per block (L2 traffic 256 x 16KB = 4MB)
// ---------------------------------------------------------------------------
__global__ __launch_bounds__(256) void k_rank16() {
    int b = blockIdx.x;         // 256 blocks
    int tid = threadIdx.x;
    int i0 = b * 16;
    __shared__ float sv[16];
    __shared__ int scnt[16];
    if (tid < 16) { sv[tid] = g_s2[i0 + tid]; scnt[tid] = 0; }
    __syncthreads();
    int cnt[16];
    #pragma unroll
    for (int q = 0; q < 16; q++) cnt[q] = 0;
    for (int j = tid; j < KDIM; j += 256) {
        float u = g_s2[j];
        #pragma unroll
        for (int q = 0; q < 16; q++) {
            float v = sv[q];
            cnt[q] += (u < v) || (u == v && j < i0 + q);
        }
    }
    #pragma unroll
    for (int q = 0; q < 16; q++) {
        int r = cnt[q];
        #pragma unroll
        for (int o = 16; o > 0; o >>= 1) r += __shfl_down_sync(0xffffffffu, r, o);
        if ((tid & 31) == 0) atomicAdd(&scnt[q], r);
    }
    __syncthreads();
    if (tid < 16) {
        int r = scnt[tid];
        int i = i0 + tid;
        g_sorted[r] = sv[tid];
        g_sigma[r] = i;
        g_ebS[r] = g_eb[i];
        g_edS[r] = g_ed[i];
    }
}

// ---------------------------------------------------------------------------
// K3: scalar global suffix sums (shfl-based, 2 syncs per pass)
// ---------------------------------------------------------------------------
__global__ void k_sscan() {
    int t = threadIdx.x;     // 1024
    int lane = t & 31, wq = t >> 5;
    __shared__ float wtot[32], wsuf[32];
    #pragma unroll
    for (int pass = 0; pass < 2; pass++) {
        const float* src = pass ? g_edS : g_ebS;
        float* dst = pass ? g_sd : g_sb;
        float e0 = src[4 * t], e1 = src[4 * t + 1], e2 = src[4 * t + 2], e3 = src[4 * t + 3];
        float part = e0 + e1 + e2 + e3;
        float v = part;   // inclusive suffix within warp
        #pragma unroll
        for (int o = 1; o < 32; o <<= 1) {
            float u = __shfl_down_sync(0xffffffffu, v, o);
            if (lane + o < 32) v += u;
        }
        if (lane == 0) wtot[wq] = v;
        __syncthreads();
        if (wq == 0) {
            float wv = wtot[lane];
            float s = wv;
            #pragma unroll
            for (int o = 1; o < 32; o <<= 1) {
                float u = __shfl_down_sync(0xffffffffu, s, o);
                if (lane + o < 32) s += u;
            }
            wsuf[lane] = s - wv;   // exclusive suffix of later warps
        }
        __syncthreads();
        float beyond = (v - part) + wsuf[wq];
        float s3 = e3 + beyond;
        float s2v = e2 + s3;
        float s1v = e1 + s2v;
        float s0 = e0 + s1v;
        dst[4 * t]     = s0;
        dst[4 * t + 1] = s1v;
        dst[4 * t + 2] = s2v;
        dst[4 * t + 3] = s3;
        if (t == 0) dst[KDIM] = 0.f;
        __syncthreads();
    }
}

// ---------------------------------------------------------------------------
// K4: zero bucket counters (graph-replay determinism)
// ---------------------------------------------------------------------------
__global__ void k_zero() { g_bcnt[threadIdx.x] = 0; }

// ---------------------------------------------------------------------------
// K5: per-row rank t_i, normalized weights, bucket assignment
// ---------------------------------------------------------------------------
__global__ __launch_bounds__(256) void k_assign() {
    int i = blockIdx.x * 256 + threadIdx.x;
    float key = -g_s1[i];
    int lo = 0, hi = KDIM;
    while (lo < hi) {
        int mid = (lo + hi) >> 1;
        if (g_sorted[mid] <= key) lo = mid + 1;
        else hi = mid;
    }
    int t = lo;
    float a = g_ea[i], c = g_ec[i];
    float Z = a * g_sb[t] + c * (g_sd[0] - g_sd[t]);
    float rZ = 1.f / Z;
    g_aZ[i] = a * rZ;
    g_cZ[i] = c * rZ;
    int b, tl;
    if (t < KDIM) { b = t / CH; tl = t - b * CH; }
    else          { b = i & (NCHUNK - 1); tl = -1; }   // neg-only rows, spread
    g_tloc[i] = tl;
    g_bkt[i] = b;
    g_slot[i] = atomicAdd(&g_bcnt[b], 1);
}

// ---------------------------------------------------------------------------
// K6: bucket offsets (prefix) + scatter rows into g_list (single block)
// ---------------------------------------------------------------------------
__global__ void k_offscatter() {
    int t = threadIdx.x;   // 256
    int lane = t & 31, wq = t >> 5;
    __shared__ int soff[256];
    __shared__ int wt[8];
    int c = g_bcnt[t];
    int v = c;
    #pragma unroll
    for (int o = 1; o < 32; o <<= 1) {
        int u = __shfl_up_sync(0xffffffffu, v, o);
        if (lane >= o) v += u;
    }
    if (lane == 31) wt[wq] = v;
    __syncthreads();
    if (t == 0) {
        int s = 0;
        #pragma unroll
        for (int q = 0; q < 8; q++) { int x = wt[q]; wt[q] = s; s += x; }
    }
    __syncthreads();
    int excl = v - c + wt[wq];
    soff[t] = excl;
    g_boff[t] = excl;
    if (t == 255) g_boff[256] = KDIM;
    __syncthreads();
    for (int i = t; i < KDIM; i += 256) {
        int pos = soff[g_bkt[i]] + g_slot[i];
        g_list[pos] = i;
    }
}

// ---------------------------------------------------------------------------
// K7: per-chunk vector totals only (no per-rank stores)
// ---------------------------------------------------------------------------
__global__ __launch_bounds__(256, 2) void k_totals(const float* __restrict__ x) {
    int c = blockIdx.x;
    int tid = threadIdx.x;
    int col = tid * 4;
    __shared__ int ssig[CH];
    __shared__ float scb[CH], scd[CH];
    if (tid < CH) {
        int k = c * CH + tid;
        ssig[tid] = g_sigma[k];
        scb[tid] = g_ebS[k];
        scd[tid] = g_edS[k];
    }
    __syncthreads();
    float4 y[CH];
    #pragma unroll
    for (int r = 0; r < CH; r++)
        y[r] = __ldg(reinterpret_cast<const float4*>(x + (size_t)ssig[r] * NDIM + col));
    float4 aB = make_float4(0.f, 0.f, 0.f, 0.f);
    float4 aD = make_float4(0.f, 0.f, 0.f, 0.f);
    #pragma unroll
    for (int r = CH - 1; r >= 0; r--) {
        float cb = scb[r], cd = scd[r];
        aB.x = fmaf(cb, y[r].x, aB.x); aB.y = fmaf(cb, y[r].y, aB.y);
        aB.z = fmaf(cb, y[r].z, aB.z); aB.w = fmaf(cb, y[r].w, aB.w);
        aD.x = fmaf(cd, y[r].x, aD.x); aD.y = fmaf(cd, y[r].y, aD.y);
        aD.z = fmaf(cd, y[r].z, aD.z); aD.w = fmaf(cd, y[r].w, aD.w);
    }
    *reinterpret_cast<float4*>(g_totBc + (size_t)c * NDIM + col) = aB;
    *reinterpret_cast<float4*>(g_totDc + (size_t)c * NDIM + col) = aD;
}

// ---------------------------------------------------------------------------
// K8: carries = exclusive suffix of chunk totals; also full TotD vector
// ---------------------------------------------------------------------------
__global__ __launch_bounds__(256) void k_carry() {
    int col = blockIdx.x * 256 + threadIdx.x;
    float aB = 0.f, aD = 0.f;
    for (int g = NCHUNK / 16 - 1; g >= 0; g--) {
        float tB[16], tD[16];
        #pragma unroll
        for (int q = 0; q < 16; q++) {
            size_t ro = (size_t)(g * 16 + q) * NDIM + col;
            tB[q] = g_totBc[ro];
            tD[q] = g_totDc[ro];
        }
        #pragma unroll
        for (int q = 15; q >= 0; q--) {
            int c = g * 16 + q;
            g_carB[(size_t)c * NDIM + col] = aB;
            g_carD[(size_t)c * NDIM + col] = aD;
            aB += tB[q];
            aD += tD[q];
        }
    }
    g_totD[col] = aD;
}

// ---------------------------------------------------------------------------
// K9: fused suffix-walk + output emission. Block = chunk c.
// Re-walks the in-register chunk suffix; at step r emits all rows with
// tloc == r:   h = aZ*(localB + carB[c]) + cZ*(TotD - (localD + carD[c]))
// Rows with tloc == -1 (positive part empty): h = cZ * TotD.
// ---------------------------------------------------------------------------
#define WAVE 128
__global__ __launch_bounds__(256, 2) void k_pass2(const float* __restrict__ x,
                                                  float* __restrict__ out) {
    int c = blockIdx.x;
    int tid = threadIdx.x;
    int col = tid * 4;
    __shared__ int ssig[CH];
    __shared__ float scb[CH], scd[CH];
    __shared__ int stl[WAVE], srow[WAVE];
    __shared__ float saZ[WAVE], scZ[WAVE];
    if (tid < CH) {
        int k = c * CH + tid;
        ssig[tid] = g_sigma[k];
        scb[tid] = g_ebS[k];
        scd[tid] = g_edS[k];
    }
    __syncthreads();

    int base = g_boff[c];
    int nb = g_boff[c + 1] - base;

    float4 y[CH];
    #pragma unroll
    for (int r = 0; r < CH; r++)
        y[r] = __ldg(reinterpret_cast<const float4*>(x + (size_t)ssig[r] * NDIM + col));

    float4 cB = *reinterpret_cast<const float4*>(g_carB + (size_t)c * NDIM + col);
    float4 cD = *reinterpret_cast<const float4*>(g_carD + (size_t)c * NDIM + col);
    float4 tD = *reinterpret_cast<const float4*>(g_totD + col);

    for (int w0 = 0; w0 < nb; w0 += WAVE) {
        int nw = min(WAVE, nb - w0);
        __syncthreads();
        if (tid < nw) {
            int row = g_list[base + w0 + tid];
            stl[tid] = g_tloc[row];
            srow[tid] = row;
            saZ[tid] = g_aZ[row];
            scZ[tid] = g_cZ[row];
        }
        __syncthreads();

        float4 aB = make_float4(0.f, 0.f, 0.f, 0.f);
        float4 aD = make_float4(0.f, 0.f, 0.f, 0.f);
        #pragma unroll
        for (int r = CH - 1; r >= 0; r--) {
            float cb = scb[r], cd = scd[r];
            aB.x = fmaf(cb, y[r].x, aB.x); aB.y = fmaf(cb, y[r].y, aB.y);
            aB.z = fmaf(cb, y[r].z, aB.z); aB.w = fmaf(cb, y[r].w, aB.w);
            aD.x = fmaf(cd, y[r].x, aD.x); aD.y = fmaf(cd, y[r].y, aD.y);
            aD.z = fmaf(cd, y[r].z, aD.z); aD.w = fmaf(cd, y[r].w, aD.w);
            for (int q = 0; q < nw; q++) {
                if (stl[q] == r) {
                    float aZ = saZ[q], cZ = scZ[q];
                    float4 h;
                    h.x = aZ * (aB.x + cB.x) + cZ * (tD.x - (aD.x + cD.x));
                    h.y = aZ * (aB.y + cB.y) + cZ * (tD.y - (aD.y + cD.y));
                    h.z = aZ * (aB.z + cB.z) + cZ * (tD.z - (aD.z + cD.z));
                    h.w = aZ * (aB.w + cB.w) + cZ * (tD.w - (aD.w + cD.w));
                    *reinterpret_cast<float4*>(out + (size_t)srow[q] * NDIM + col) = h;
                }
            }
        }
        for (int q = 0; q < nw; q++) {
            if (stl[q] == -1) {
                float cZ = scZ[q];
                float4 h = make_float4(cZ * tD.x, cZ * tD.y, cZ * tD.z, cZ * tD.w);
                *reinterpret_cast<float4*>(out + (size_t)srow[q] * NDIM + col) = h;
            }
        }
    }
}

// ---------------------------------------------------------------------------
extern "C" void kernel_launch(void* const* d_in, const int* in_sizes, int n_in,
                              void* d_out, int out_size) {
    const float* x = (const float*)d_in[0];   // (4096, 1024) fp32
    const float* w = (const float*)d_in[1];   // (2048, 1) fp32
    float* out = (float*)d_out;               // (4096, 1024) fp32

    k_scores<<<KDIM, 256>>>(x, w);
    k_rank16<<<NCHUNK, 256>>>();
    k_sscan<<<1, 1024>>>();
    k_zero<<<1, NCHUNK>>>();
    k_assign<<<KDIM / 256, 256>>>();
    k_offscatter<<<1, 256>>>();
    k_totals<<<NCHUNK, 256>>>(x);
    k_carry<<<4, 256>>>();
    k_pass2<<<NCHUNK, 256>>>(x, out);
}

// round 7
// speedup vs baseline: 1.3937x; 1.3937x over previous
#include <cuda_runtime.h>
#include <cuda_bf16.h>
#include <cstdint>

#define ALPHA 0.2f
#define KDIM 4096
#define NDIM 1024
#define CH 16
#define NCHUNK (KDIM / CH)   // 256

// ---------------- scratch (__device__ globals; no allocs allowed) ----------
__device__ float g_s1[KDIM], g_s2[KDIM];
__device__ float g_ea[KDIM], g_ec[KDIM];        // exp(s1), exp(0.2 s1)
__device__ float g_eb[KDIM], g_ed[KDIM];        // exp(s2), exp(0.2 s2)
__device__ float g_sorted[KDIM];                // s2 ascending
__device__ int   g_sigma[KDIM];                 // sorted rank -> original index
__device__ float g_ebS[KDIM], g_edS[KDIM];      // eb/ed in sorted order
__device__ float g_sb[KDIM + 1], g_sd[KDIM + 1];// scalar global suffix sums
__device__ float g_sufB[(size_t)KDIM * NDIM];   // chunk-local vector suffix sums (16MB)
__device__ float g_sufD[(size_t)KDIM * NDIM];   // 16MB
__device__ float g_carB[NCHUNK * NDIM];         // chunk carries (exclusive suffix of totals)
__device__ float g_carD[NCHUNK * NDIM];

// ---------------------------------------------------------------------------
// K1: s1/s2 GEMV + exp factors. 1024 blocks x 4 rows, loads batched for MLP.
// ---------------------------------------------------------------------------
__global__ __launch_bounds__(256) void k_scores(const float* __restrict__ x,
                                                const float* __restrict__ w) {
    int b = blockIdx.x;           // 1024
    int t = threadIdx.x;          // 256 threads * float4 = 1024 cols
    int i0 = b * 4;
    const float4* w1 = reinterpret_cast<const float4*>(w);
    const float4* w2 = reinterpret_cast<const float4*>(w + NDIM);
    float4 a = __ldg(w1 + t);
    float4 bb = __ldg(w2 + t);
    float4 xv[4];
    #pragma unroll
    for (int r = 0; r < 4; r++)
        xv[r] = __ldg(reinterpret_cast<const float4*>(x + (size_t)(i0 + r) * NDIM) + t);

    __shared__ float sm1[4][8], sm2[4][8];
    #pragma unroll
    for (int r = 0; r < 4; r++) {
        float d1 = xv[r].x * a.x + xv[r].y * a.y + xv[r].z * a.z + xv[r].w * a.w;
        float d2 = xv[r].x * bb.x + xv[r].y * bb.y + xv[r].z * bb.z + xv[r].w * bb.w;
        #pragma unroll
        for (int o = 16; o > 0; o >>= 1) {
            d1 += __shfl_down_sync(0xffffffffu, d1, o);
            d2 += __shfl_down_sync(0xffffffffu, d2, o);
        }
        if ((t & 31) == 0) { sm1[r][t >> 5] = d1; sm2[r][t >> 5] = d2; }
    }
    __syncthreads();
    if (t < 4) {
        float s1 = 0.f, s2 = 0.f;
        #pragma unroll
        for (int q = 0; q < 8; q++) { s1 += sm1[t][q]; s2 += sm2[t][q]; }
        int i = i0 + t;
        g_s1[i] = s1;
        g_s2[i] = s2;
        g_ea[i] = __expf(s1);
        g_ec[i] = __expf(ALPHA * s1);
        g_eb[i] = __expf(s2);
        g_ed[i] = __expf(ALPHA * s2);
    }
}

// ---------------------------------------------------------------------------
// K2: ranks, 16 rows per block (256 blocks, ~4MB L2 traffic)
// ---------------------------------------------------------------------------
__global__ __launch_bounds__(256) void k_rank16() {
    int b = blockIdx.x;         // 256 blocks
    int tid = threadIdx.x;
    int i0 = b * 16;
    __shared__ float sv[16];
    __shared__ int scnt[16];
    if (tid < 16) { sv[tid] = g_s2[i0 + tid]; scnt[tid] = 0; }
    __syncthreads();
    int cnt[16];
    #pragma unroll
    for (int q = 0; q < 16; q++) cnt[q] = 0;
    for (int j = tid; j < KDIM; j += 256) {
        float u = g_s2[j];
        #pragma unroll
        for (int q = 0; q < 16; q++) {
            float v = sv[q];
            cnt[q] += (u < v) || (u == v && j < i0 + q);
        }
    }
    #pragma unroll
    for (int q = 0; q < 16; q++) {
        int r = cnt[q];
        #pragma unroll
        for (int o = 16; o > 0; o >>= 1) r += __shfl_down_sync(0xffffffffu, r, o);
        if ((tid & 31) == 0) atomicAdd(&scnt[q], r);
    }
    __syncthreads();
    if (tid < 16) {
        int r = scnt[tid];
        int i = i0 + tid;
        g_sorted[r] = sv[tid];
        g_sigma[r] = i;
        g_ebS[r] = g_eb[i];
        g_edS[r] = g_ed[i];
    }
}

// ---------------------------------------------------------------------------
// K3: chunk-local vector suffix sums. Block = chunk of CH=16 sorted rows,
// all 16 gathered rows loaded up-front into registers (MLP=16).
// ---------------------------------------------------------------------------
__global__ __launch_bounds__(256, 2) void k_scan(const float* __restrict__ x) {
    int c = blockIdx.x;
    int tid = threadIdx.x;
    int col = tid * 4;
    __shared__ int ssig[CH];
    __shared__ float scb[CH], scd[CH];
    if (tid < CH) {
        int k = c * CH + tid;
        ssig[tid] = g_sigma[k];
        scb[tid] = g_ebS[k];
        scd[tid] = g_edS[k];
    }
    __syncthreads();

    float4 y[CH];
    #pragma unroll
    for (int r = 0; r < CH; r++)
        y[r] = __ldg(reinterpret_cast<const float4*>(x + (size_t)ssig[r] * NDIM + col));

    float4 aB = make_float4(0.f, 0.f, 0.f, 0.f);
    float4 aD = make_float4(0.f, 0.f, 0.f, 0.f);

    #pragma unroll
    for (int r = CH - 1; r >= 0; r--) {
        float cb = scb[r], cd = scd[r];
        aB.x = fmaf(cb, y[r].x, aB.x); aB.y = fmaf(cb, y[r].y, aB.y);
        aB.z = fmaf(cb, y[r].z, aB.z); aB.w = fmaf(cb, y[r].w, aB.w);
        aD.x = fmaf(cd, y[r].x, aD.x); aD.y = fmaf(cd, y[r].y, aD.y);
        aD.z = fmaf(cd, y[r].z, aD.z); aD.w = fmaf(cd, y[r].w, aD.w);
        size_t ro = (size_t)(c * CH + r) * NDIM + col;
        *reinterpret_cast<float4*>(g_sufB + ro) = aB;
        *reinterpret_cast<float4*>(g_sufD + ro) = aD;
    }
}

// ---------------------------------------------------------------------------
// K4: 5 blocks. Blocks 0-3: chunk carries (exclusive suffix of chunk totals,
// per column). Block 4: scalar global suffix sums of ebS/edS (256 threads,
// 16 elems/thread).
// ---------------------------------------------------------------------------
__global__ __launch_bounds__(256) void k_carry() {
    int tid = threadIdx.x;
    if (blockIdx.x < 4) {
        int col = blockIdx.x * 256 + tid;
        float aB = 0.f, aD = 0.f;
        for (int g = NCHUNK / 16 - 1; g >= 0; g--) {
            float tB[16], tD[16];
            #pragma unroll
            for (int q = 0; q < 16; q++) {
                size_t ro = (size_t)((g * 16 + q) * CH) * NDIM + col;
                tB[q] = g_sufB[ro];
                tD[q] = g_sufD[ro];
            }
            #pragma unroll
            for (int q = 15; q >= 0; q--) {
                int c = g * 16 + q;
                g_carB[c * NDIM + col] = aB;
                g_carD[c * NDIM + col] = aD;
                aB += tB[q];
                aD += tD[q];
            }
        }
    } else {
        // scalar suffix scans: thread t owns elems [16t, 16t+16)
        int lane = tid & 31, wq = tid >> 5;
        __shared__ float wtot[8], wsuf[8];
        #pragma unroll
        for (int pass = 0; pass < 2; pass++) {
            const float* src = pass ? g_edS : g_ebS;
            float* dst = pass ? g_sd : g_sb;
            float e[16];
            float tot = 0.f;
            #pragma unroll
            for (int q = 0; q < 16; q++) { e[q] = src[16 * tid + q]; tot += e[q]; }
            float v = tot;   // inclusive suffix within warp
            #pragma unroll
            for (int o = 1; o < 32; o <<= 1) {
                float u = __shfl_down_sync(0xffffffffu, v, o);
                if (lane + o < 32) v += u;
            }
            if (lane == 0) wtot[wq] = v;
            __syncthreads();
            if (wq == 0 && lane < 8) {
                float s = 0.f;
                #pragma unroll
                for (int q = 0; q < 8; q++) s += (q > lane) ? wtot[q] : 0.f;
                wsuf[lane] = s;
            }
            __syncthreads();
            float s = (v - tot) + wsuf[wq];   // strict suffix beyond this thread
            #pragma unroll
            for (int q = 15; q >= 0; q--) {
                s += e[q];
                dst[16 * tid + q] = s;
            }
            if (tid == 0) dst[KDIM] = 0.f;
            __syncthreads();
        }
    }
}

// ---------------------------------------------------------------------------
// K5: output. Block = row i. Binary-search rank t_i of -s1_i, form
// h_i = (a_i*SufB(t) + c_i*(TotD - SufD(t))) / Z_i.
// ---------------------------------------------------------------------------
__global__ __launch_bounds__(256) void k_out(float* __restrict__ out) {
    int i = blockIdx.x;
    int tid = threadIdx.x;
    __shared__ int sT;
    __shared__ float sAZ, sCZ;
    if (tid == 0) {
        float key = -g_s1[i];
        int lo = 0, hi = KDIM;
        while (lo < hi) {
            int mid = (lo + hi) >> 1;
            if (g_sorted[mid] <= key) lo = mid + 1;
            else hi = mid;
        }
        int t = lo;
        float a = g_ea[i], c = g_ec[i];
        float Z = a * g_sb[t] + c * (g_sd[0] - g_sd[t]);
        float rZ = 1.f / Z;
        sT = t;
        sAZ = a * rZ;
        sCZ = c * rZ;
    }
    __syncthreads();
    int t = sT;
    float aZ = sAZ, cZ = sCZ;
    int col = tid * 4;

    bool in = (t < KDIM);
    int tt = in ? t : 0;
    int ch = tt / CH;
    size_t ro = (size_t)tt * NDIM + col;
    size_t co = (size_t)ch * NDIM + col;

    float4 sB = *reinterpret_cast<const float4*>(g_sufB + ro);
    float4 cB = *reinterpret_cast<const float4*>(g_carB + co);
    float4 sD = *reinterpret_cast<const float4*>(g_sufD + ro);
    float4 cD = *reinterpret_cast<const float4*>(g_carD + co);
    float4 sD0 = *reinterpret_cast<const float4*>(g_sufD + col);
    float4 cD0 = *reinterpret_cast<const float4*>(g_carD + col);

    float m = in ? 1.f : 0.f;  // t == KDIM: positive part empty, neg = full total
    float4 h;
    h.x = aZ * m * (sB.x + cB.x) + cZ * ((sD0.x + cD0.x) - m * (sD.x + cD.x));
    h.y = aZ * m * (sB.y + cB.y) + cZ * ((sD0.y + cD0.y) - m * (sD.y + cD.y));
    h.z = aZ * m * (sB.z + cB.z) + cZ * ((sD0.z + cD0.z) - m * (sD.z + cD.z));
    h.w = aZ * m * (sB.w + cB.w) + cZ * ((sD0.w + cD0.w) - m * (sD.w + cD.w));

    *reinterpret_cast<float4*>(out + (size_t)i * NDIM + col) = h;
}

// ---------------------------------------------------------------------------
extern "C" void kernel_launch(void* const* d_in, const int* in_sizes, int n_in,
                              void* d_out, int out_size) {
    const float* x = (const float*)d_in[0];   // (4096, 1024) fp32
    const float* w = (const float*)d_in[1];   // (2048, 1) fp32
    float* out = (float*)d_out;               // (4096, 1024) fp32

    k_scores<<<KDIM / 4, 256>>>(x, w);
    k_rank16<<<NCHUNK, 256>>>();
    k_scan<<<NCHUNK, 256>>>(x);
    k_carry<<<5, 256>>>();
    k_out<<<KDIM, 256>>>(out);
}

// round 8
// speedup vs baseline: 1.5120x; 1.0849x over previous
#include <cuda_runtime.h>
#include <cuda_bf16.h>
#include <cstdint>

#define ALPHA 0.2f
#define KDIM 4096
#define NDIM 1024
#define CH 16
#define NCHUNK (KDIM / CH)   // 256

// ---------------- scratch (__device__ globals; no allocs allowed) ----------
__device__ float g_s1[KDIM], g_s2[KDIM];
__device__ float g_ea[KDIM], g_ec[KDIM];        // exp(s1), exp(0.2 s1)
__device__ float g_eb[KDIM], g_ed[KDIM];        // exp(s2), exp(0.2 s2)
__device__ float g_sorted[KDIM];                // s2 ascending
__device__ int   g_sigma[KDIM];                 // sorted rank -> original index
__device__ float g_ebS[KDIM], g_edS[KDIM];      // eb/ed in sorted order
__device__ float g_sb[KDIM + 1], g_sd[KDIM + 1];// scalar global suffix sums
__device__ float g_sufB[(size_t)KDIM * NDIM];   // chunk-local vector suffix sums (16MB)
__device__ float g_sufD[(size_t)KDIM * NDIM];   // 16MB
__device__ float g_carB[NCHUNK * NDIM];         // chunk carries (exclusive suffix of totals)
__device__ float g_carD[NCHUNK * NDIM];

// ---------------------------------------------------------------------------
// K1: s1/s2 GEMV + exp factors. 1024 blocks x 4 rows, loads batched for MLP.
// ---------------------------------------------------------------------------
__global__ __launch_bounds__(256) void k_scores(const float* __restrict__ x,
                                                const float* __restrict__ w) {
    int b = blockIdx.x;           // 1024
    int t = threadIdx.x;          // 256 threads * float4 = 1024 cols
    int i0 = b * 4;
    const float4* w1 = reinterpret_cast<const float4*>(w);
    const float4* w2 = reinterpret_cast<const float4*>(w + NDIM);
    float4 a = __ldg(w1 + t);
    float4 bb = __ldg(w2 + t);
    float4 xv[4];
    #pragma unroll
    for (int r = 0; r < 4; r++)
        xv[r] = __ldg(reinterpret_cast<const float4*>(x + (size_t)(i0 + r) * NDIM) + t);

    __shared__ float sm1[4][8], sm2[4][8];
    #pragma unroll
    for (int r = 0; r < 4; r++) {
        float d1 = xv[r].x * a.x + xv[r].y * a.y + xv[r].z * a.z + xv[r].w * a.w;
        float d2 = xv[r].x * bb.x + xv[r].y * bb.y + xv[r].z * bb.z + xv[r].w * bb.w;
        #pragma unroll
        for (int o = 16; o > 0; o >>= 1) {
            d1 += __shfl_down_sync(0xffffffffu, d1, o);
            d2 += __shfl_down_sync(0xffffffffu, d2, o);
        }
        if ((t & 31) == 0) { sm1[r][t >> 5] = d1; sm2[r][t >> 5] = d2; }
    }
    __syncthreads();
    if (t < 4) {
        float s1 = 0.f, s2 = 0.f;
        #pragma unroll
        for (int q = 0; q < 8; q++) { s1 += sm1[t][q]; s2 += sm2[t][q]; }
        int i = i0 + t;
        g_s1[i] = s1;
        g_s2[i] = s2;
        g_ea[i] = __expf(s1);
        g_ec[i] = __expf(ALPHA * s1);
        g_eb[i] = __expf(s2);
        g_ed[i] = __expf(ALPHA * s2);
    }
}

// ---------------------------------------------------------------------------
// K2: ranks, 16 rows per block (256 blocks, ~4MB L2 traffic)
// ---------------------------------------------------------------------------
__global__ __launch_bounds__(256) void k_rank16() {
    int b = blockIdx.x;         // 256 blocks
    int tid = threadIdx.x;
    int i0 = b * 16;
    __shared__ float sv[16];
    __shared__ int scnt[16];
    if (tid < 16) { sv[tid] = g_s2[i0 + tid]; scnt[tid] = 0; }
    __syncthreads();
    int cnt[16];
    #pragma unroll
    for (int q = 0; q < 16; q++) cnt[q] = 0;
    for (int j = tid; j < KDIM; j += 256) {
        float u = g_s2[j];
        #pragma unroll
        for (int q = 0; q < 16; q++) {
            float v = sv[q];
            cnt[q] += (u < v) || (u == v && j < i0 + q);
        }
    }
    #pragma unroll
    for (int q = 0; q < 16; q++) {
        int r = cnt[q];
        #pragma unroll
        for (int o = 16; o > 0; o >>= 1) r += __shfl_down_sync(0xffffffffu, r, o);
        if ((tid & 31) == 0) atomicAdd(&scnt[q], r);
    }
    __syncthreads();
    if (tid < 16) {
        int r = scnt[tid];
        int i = i0 + tid;
        g_sorted[r] = sv[tid];
        g_sigma[r] = i;
        g_ebS[r] = g_eb[i];
        g_edS[r] = g_ed[i];
    }
}

// ---------------------------------------------------------------------------
// K3: chunk-local vector suffix sums. Block = chunk of CH=16 sorted rows,
// all 16 gathered rows loaded up-front into registers (MLP=16).
// ---------------------------------------------------------------------------
__global__ __launch_bounds__(256, 2) void k_scan(const float* __restrict__ x) {
    int c = blockIdx.x;
    int tid = threadIdx.x;
    int col = tid * 4;
    __shared__ int ssig[CH];
    __shared__ float scb[CH], scd[CH];
    if (tid < CH) {
        int k = c * CH + tid;
        ssig[tid] = g_sigma[k];
        scb[tid] = g_ebS[k];
        scd[tid] = g_edS[k];
    }
    __syncthreads();

    float4 y[CH];
    #pragma unroll
    for (int r = 0; r < CH; r++)
        y[r] = __ldg(reinterpret_cast<const float4*>(x + (size_t)ssig[r] * NDIM + col));

    float4 aB = make_float4(0.f, 0.f, 0.f, 0.f);
    float4 aD = make_float4(0.f, 0.f, 0.f, 0.f);

    #pragma unroll
    for (int r = CH - 1; r >= 0; r--) {
        float cb = scb[r], cd = scd[r];
        aB.x = fmaf(cb, y[r].x, aB.x); aB.y = fmaf(cb, y[r].y, aB.y);
        aB.z = fmaf(cb, y[r].z, aB.z); aB.w = fmaf(cb, y[r].w, aB.w);
        aD.x = fmaf(cd, y[r].x, aD.x); aD.y = fmaf(cd, y[r].y, aD.y);
        aD.z = fmaf(cd, y[r].z, aD.z); aD.w = fmaf(cd, y[r].w, aD.w);
        size_t ro = (size_t)(c * CH + r) * NDIM + col;
        *reinterpret_cast<float4*>(g_sufB + ro) = aB;
        *reinterpret_cast<float4*>(g_sufD + ro) = aD;
    }
}

// ---------------------------------------------------------------------------
// K4: hierarchical carries. Blocks 0-63: 16 columns x 16 chunk-groups each.
// Thread (cg, col) loads its group's 16 chunk totals (MLP=16), computes the
// within-group exclusive suffix in registers, publishes group totals to smem,
// then adds the strict suffix of later groups. Block 64: scalar sscan.
// ---------------------------------------------------------------------------
__global__ __launch_bounds__(256) void k_carry() {
    int tid = threadIdx.x;
    if (blockIdx.x < 64) {
        int ci = tid & 15;                  // column within block
        int cg = tid >> 4;                  // chunk group 0..15
        int col = blockIdx.x * 16 + ci;
        __shared__ float sgB[16][17], sgD[16][17];

        float tB[16], tD[16];
        #pragma unroll
        for (int q = 0; q < 16; q++) {
            size_t ro = (size_t)((cg * 16 + q) * CH) * NDIM + col;
            tB[q] = g_sufB[ro];
            tD[q] = g_sufD[ro];
        }
        float wcB[16], wcD[16];
        float sB = 0.f, sD = 0.f;
        #pragma unroll
        for (int q = 15; q >= 0; q--) {
            wcB[q] = sB; wcD[q] = sD;
            sB += tB[q]; sD += tD[q];
        }
        sgB[cg][ci] = sB;                   // group totals
        sgD[cg][ci] = sD;
        __syncthreads();
        float gB = 0.f, gD = 0.f;
        #pragma unroll
        for (int g = 0; g < 16; g++) {
            if (g > cg) { gB += sgB[g][ci]; gD += sgD[g][ci]; }
        }
        #pragma unroll
        for (int q = 0; q < 16; q++) {
            int c = cg * 16 + q;
            g_carB[c * NDIM + col] = wcB[q] + gB;
            g_carD[c * NDIM + col] = wcD[q] + gD;
        }
    } else {
        // scalar suffix scans: thread t owns elems [16t, 16t+16)
        int lane = tid & 31, wq = tid >> 5;
        __shared__ float wtot[8], wsuf[8];
        #pragma unroll
        for (int pass = 0; pass < 2; pass++) {
            const float* src = pass ? g_edS : g_ebS;
            float* dst = pass ? g_sd : g_sb;
            float e[16];
            float tot = 0.f;
            #pragma unroll
            for (int q = 0; q < 16; q++) { e[q] = src[16 * tid + q]; tot += e[q]; }
            float v = tot;   // inclusive suffix within warp
            #pragma unroll
            for (int o = 1; o < 32; o <<= 1) {
                float u = __shfl_down_sync(0xffffffffu, v, o);
                if (lane + o < 32) v += u;
            }
            if (lane == 0) wtot[wq] = v;
            __syncthreads();
            if (wq == 0 && lane < 8) {
                float s = 0.f;
                #pragma unroll
                for (int q = 0; q < 8; q++) s += (q > lane) ? wtot[q] : 0.f;
                wsuf[lane] = s;
            }
            __syncthreads();
            float s = (v - tot) + wsuf[wq];   // strict suffix beyond this thread
            #pragma unroll
            for (int q = 15; q >= 0; q--) {
                s += e[q];
                dst[16 * tid + q] = s;
            }
            if (tid == 0) dst[KDIM] = 0.f;
            __syncthreads();
        }
    }
}

// ---------------------------------------------------------------------------
// K5: output. Block = row i. Binary-search rank t_i of -s1_i, form
// h_i = (a_i*SufB(t) + c_i*(TotD - SufD(t))) / Z_i.
// ---------------------------------------------------------------------------
__global__ __launch_bounds__(256) void k_out(float* __restrict__ out) {
    int i = blockIdx.x;
    int tid = threadIdx.x;
    __shared__ int sT;
    __shared__ float sAZ, sCZ;
    if (tid == 0) {
        float key = -g_s1[i];
        int lo = 0, hi = KDIM;
        while (lo < hi) {
            int mid = (lo + hi) >> 1;
            if (g_sorted[mid] <= key) lo = mid + 1;
            else hi = mid;
        }
        int t = lo;
        float a = g_ea[i], c = g_ec[i];
        float Z = a * g_sb[t] + c * (g_sd[0] - g_sd[t]);
        float rZ = 1.f / Z;
        sT = t;
        sAZ = a * rZ;
        sCZ = c * rZ;
    }
    __syncthreads();
    int t = sT;
    float aZ = sAZ, cZ = sCZ;
    int col = tid * 4;

    bool in = (t < KDIM);
    int tt = in ? t : 0;
    int ch = tt / CH;
    size_t ro = (size_t)tt * NDIM + col;
    size_t co = (size_t)ch * NDIM + col;

    float4 sB = *reinterpret_cast<const float4*>(g_sufB + ro);
    float4 cB = *reinterpret_cast<const float4*>(g_carB + co);
    float4 sD = *reinterpret_cast<const float4*>(g_sufD + ro);
    float4 cD = *reinterpret_cast<const float4*>(g_carD + co);
    float4 sD0 = *reinterpret_cast<const float4*>(g_sufD + col);
    float4 cD0 = *reinterpret_cast<const float4*>(g_carD + col);

    float m = in ? 1.f : 0.f;  // t == KDIM: positive part empty, neg = full total
    float4 h;
    h.x = aZ * m * (sB.x + cB.x) + cZ * ((sD0.x + cD0.x) - m * (sD.x + cD.x));
    h.y = aZ * m * (sB.y + cB.y) + cZ * ((sD0.y + cD0.y) - m * (sD.y + cD.y));
    h.z = aZ * m * (sB.z + cB.z) + cZ * ((sD0.z + cD0.z) - m * (sD.z + cD.z));
    h.w = aZ * m * (sB.w + cB.w) + cZ * ((sD0.w + cD0.w) - m * (sD.w + cD.w));

    *reinterpret_cast<float4*>(out + (size_t)i * NDIM + col) = h;
}

// ---------------------------------------------------------------------------
extern "C" void kernel_launch(void* const* d_in, const int* in_sizes, int n_in,
                              void* d_out, int out_size) {
    const float* x = (const float*)d_in[0];   // (4096, 1024) fp32
    const float* w = (const float*)d_in[1];   // (2048, 1) fp32
    float* out = (float*)d_out;               // (4096, 1024) fp32

    k_scores<<<KDIM / 4, 256>>>(x, w);
    k_rank16<<<NCHUNK, 256>>>();
    k_scan<<<NCHUNK, 256>>>(x);
    k_carry<<<65, 256>>>();
    k_out<<<KDIM, 256>>>(out);
}